// round 16
// baseline (speedup 1.0000x reference)
#include <cuda_runtime.h>
#include <cuda_bf16.h>
#include <math.h>
#include <cstdint>

#define HIDDEN 2048
#define NH 16
#define NKV 4
#define HD 128
#define KVD 512
#define WINDOW 1024
#define BATCH 2
#define SEQ 2048
#define MTOK 4096
#define GK 2048

// ---------------- scratch (static device globals; no allocation) ----------------
__device__ __nv_bfloat16 g_xh[MTOK * GK], g_xl[MTOK * GK];
__device__ __nv_bfloat16 g_qb[MTOK * HIDDEN];
__device__ __nv_bfloat16 g_kb[MTOK * KVD];
__device__ __nv_bfloat16 g_vh[MTOK * KVD], g_vl[MTOK * KVD];
__device__ float g_tmp[MTOK * KVD];   // V-proj partial (fp32)
__device__ __nv_bfloat16 g_wqh[HIDDEN * GK], g_wql[HIDDEN * GK];
__device__ __nv_bfloat16 g_wkh[KVD * GK],    g_wkl[KVD * GK];
__device__ __nv_bfloat16 g_wvh[KVD * GK],    g_wvl[KVD * GK];
__device__ __nv_bfloat16 g_woh[HIDDEN * GK], g_wol[HIDDEN * GK];
__device__ float g_cos[SEQ * 64], g_sin[SEQ * 64];

// ---------------- helpers --------------------------------------------------------
__device__ __forceinline__ uint32_t smem_u32(const void* p) {
    uint32_t a;
    asm("{ .reg .u64 t; cvta.to.shared.u64 t, %1; cvt.u32.u64 %0, t; }" : "=r"(a) : "l"(p));
    return a;
}
__device__ __forceinline__ void ldmx4(uint32_t* r, uint32_t addr) {
    asm volatile("ldmatrix.sync.aligned.m8n8.x4.shared.b16 {%0,%1,%2,%3}, [%4];"
                 : "=r"(r[0]), "=r"(r[1]), "=r"(r[2]), "=r"(r[3]) : "r"(addr));
}
__device__ __forceinline__ void ldmx4t(uint32_t* r, uint32_t addr) {
    asm volatile("ldmatrix.sync.aligned.m8n8.x4.trans.shared.b16 {%0,%1,%2,%3}, [%4];"
                 : "=r"(r[0]), "=r"(r[1]), "=r"(r[2]), "=r"(r[3]) : "r"(addr));
}
__device__ __forceinline__ void mma16816(float* d, const uint32_t* a, const uint32_t* b) {
    asm volatile(
        "mma.sync.aligned.m16n8k16.row.col.f32.bf16.bf16.f32 "
        "{%0,%1,%2,%3}, {%4,%5,%6,%7}, {%8,%9}, {%0,%1,%2,%3};"
        : "+f"(d[0]), "+f"(d[1]), "+f"(d[2]), "+f"(d[3])
        : "r"(a[0]), "r"(a[1]), "r"(a[2]), "r"(a[3]), "r"(b[0]), "r"(b[1]));
}
__device__ __forceinline__ void split2(float a, float b, uint32_t& hpk, uint32_t& lpk) {
    asm("cvt.rn.bf16x2.f32 %0, %1, %2;" : "=r"(hpk) : "f"(b), "f"(a));
    float fa = __uint_as_float(hpk << 16);
    float fb = __uint_as_float(hpk & 0xffff0000u);
    float ra = a - fa, rb = b - fb;
    asm("cvt.rn.bf16x2.f32 %0, %1, %2;" : "=r"(lpk) : "f"(rb), "f"(ra));
}
__device__ __forceinline__ void cpasync16(uint32_t dst, const void* src) {
    asm volatile("cp.async.cg.shared.global [%0], [%1], 16;" :: "r"(dst), "l"(src) : "memory");
}

// ---------------- GEMM via mma.sync ------------------------------------------------
// NT staged tensors: 2={Ah,Bh} 1 pass; 3={Ah,Al,Bh} 2 passes; 4={Ah,Al,Bh,Bl} 3 passes.
// EPI: 0 fp32 store (+bias), 1 rope+bf16, 2 split store (+bias), 3 fp32 accumulate-add,
//      4 read fp32 C + add + split store.
// NST: pipeline stages. msplit: -1 full grid; 0/1 token-half (grid.y = 16).
template <int NT, int EPI, int MINB, int NST>
__global__ __launch_bounds__(256, MINB) void gemm_mma(
    const __nv_bfloat16* __restrict__ Ah, const __nv_bfloat16* __restrict__ Al,
    const __nv_bfloat16* __restrict__ Bh, const __nv_bfloat16* __restrict__ Bl,
    const float* __restrict__ bias, float* __restrict__ C,
    __nv_bfloat16* __restrict__ O1, __nv_bfloat16* __restrict__ O2, int N, int msplit)
{
    extern __shared__ __align__(128) char smem[];
    const uint32_t sb = smem_u32(smem);
    const int tid  = threadIdx.x;
    const int lane = tid & 31;
    const int wid  = tid >> 5;
    const int wm   = wid >> 2;
    const int wn   = wid & 3;
    const int bn   = blockIdx.x * 128;
    int mb = blockIdx.y;
    if (msplit >= 0) mb = ((blockIdx.y >> 3) << 4) + msplit * 8 + (blockIdx.y & 7);
    const int bm   = mb * 128;

    const int STAGE = NT * 16384;
    const int BHOFF = (NT == 2) ? 16384 : 32768;

    const __nv_bfloat16* srcs[NT];
    if (NT == 2) {
        srcs[0] = Ah + (size_t)bm * GK;
        srcs[1] = Bh + (size_t)bn * GK;
    } else if (NT == 3) {
        srcs[0] = Ah + (size_t)bm * GK;
        srcs[1] = Al + (size_t)bm * GK;
        srcs[2] = Bh + (size_t)bn * GK;
    } else {
        srcs[0] = Ah + (size_t)bm * GK;
        srcs[1] = Al + (size_t)bm * GK;
        srcs[2] = Bh + (size_t)bn * GK;
        srcs[3] = Bl + (size_t)bn * GK;
    }
    const int rr = tid >> 3, cc = tid & 7;

    const int idx8   = lane & 7;
    const int a_moff = ((lane >> 3) & 1) * 8;
    const int a_coff = lane >> 4;
    const int b_noff = (lane >> 4) * 8;
    const int b_coff = (lane >> 3) & 1;

    float acc[4][4][4];
#pragma unroll
    for (int i = 0; i < 4; i++)
#pragma unroll
        for (int j = 0; j < 4; j++)
#pragma unroll
            for (int e = 0; e < 4; e++) acc[i][j][e] = 0.f;

    auto issue = [&](int c, int buf) {
        const int k0 = c * 64;
        const uint32_t st = sb + buf * STAGE;
#pragma unroll
        for (int t = 0; t < NT; t++) {
            const __nv_bfloat16* bp = srcs[t] + k0 + cc * 8;
#pragma unroll
            for (int j = 0; j < 4; j++) {
                int r = rr + 32 * j;
                int byte = r * 128 + cc * 16;
                uint32_t dst = st + t * 16384 + (byte ^ ((byte >> 3) & 0x70));
                cpasync16(dst, bp + (size_t)r * GK);
            }
        }
        asm volatile("cp.async.commit_group;" ::: "memory");
    };

#pragma unroll
    for (int p = 0; p < NST; p++) issue(p, p);

    for (int c = 0; c < 32; c++) {
        if (NST == 3) {
            if (c <= 29)      asm volatile("cp.async.wait_group 2;" ::: "memory");
            else if (c == 30) asm volatile("cp.async.wait_group 1;" ::: "memory");
            else              asm volatile("cp.async.wait_group 0;" ::: "memory");
        } else {
            if (c <= 30)      asm volatile("cp.async.wait_group 1;" ::: "memory");
            else              asm volatile("cp.async.wait_group 0;" ::: "memory");
        }
        __syncthreads();
        const uint32_t st = sb + (c % NST) * STAGE;

#pragma unroll
        for (int ks = 0; ks < 4; ks++) {
            uint32_t ah[4][4], al[4][4], bh[2][4], bl[2][4];
            const int chA = ks * 2 + a_coff;
            const int chB = ks * 2 + b_coff;
#pragma unroll
            for (int mt = 0; mt < 4; mt++) {
                int row = wm * 64 + mt * 16 + a_moff + idx8;
                uint32_t off = row * 128 + ((chA ^ (row & 7)) << 4);
                ldmx4(ah[mt], st + off);
                if (NT >= 3) ldmx4(al[mt], st + 16384 + off);
            }
#pragma unroll
            for (int h = 0; h < 2; h++) {
                int row = wn * 32 + h * 16 + b_noff + idx8;
                uint32_t off = row * 128 + ((chB ^ (row & 7)) << 4);
                ldmx4(bh[h], st + BHOFF + off);
                if (NT == 4) ldmx4(bl[h], st + 49152 + off);
            }
#pragma unroll
            for (int mt = 0; mt < 4; mt++)
#pragma unroll
                for (int nt = 0; nt < 4; nt++) {
                    const uint32_t* ph = &bh[nt >> 1][(nt & 1) * 2];
                    mma16816(acc[mt][nt], ah[mt], ph);
                    if (NT >= 3) mma16816(acc[mt][nt], al[mt], ph);
                    if (NT == 4) {
                        const uint32_t* pl = &bl[nt >> 1][(nt & 1) * 2];
                        mma16816(acc[mt][nt], ah[mt], pl);
                    }
                }
        }
        __syncthreads();
        if (c + NST < 32) issue(c + NST, (c + NST) % NST);
    }

    const int r0   = wm * 64 + (lane >> 2);
    const int c0   = wn * 32 + (lane & 3) * 2;

    if (EPI == 0) {
#pragma unroll
        for (int mt = 0; mt < 4; mt++)
#pragma unroll
            for (int nt = 0; nt < 4; nt++) {
                int row = bm + r0 + mt * 16;
                int col = bn + c0 + nt * 8;
                float b0 = 0.f, b1 = 0.f;
                if (bias) { b0 = bias[col]; b1 = bias[col + 1]; }
                *(float2*)(C + (size_t)row * N + col)       = make_float2(acc[mt][nt][0] + b0, acc[mt][nt][1] + b1);
                *(float2*)(C + (size_t)(row + 8) * N + col) = make_float2(acc[mt][nt][2] + b0, acc[mt][nt][3] + b1);
            }
    } else if (EPI == 3) {
#pragma unroll
        for (int mt = 0; mt < 4; mt++)
#pragma unroll
            for (int nt = 0; nt < 4; nt++) {
                int row = bm + r0 + mt * 16;
                int col = bn + c0 + nt * 8;
                float2* p0 = (float2*)(C + (size_t)row * N + col);
                float2* p1 = (float2*)(C + (size_t)(row + 8) * N + col);
                float2 v0 = *p0, v1 = *p1;
                v0.x += acc[mt][nt][0]; v0.y += acc[mt][nt][1];
                v1.x += acc[mt][nt][2]; v1.y += acc[mt][nt][3];
                *p0 = v0; *p1 = v1;
            }
    } else if (EPI == 4) {
#pragma unroll
        for (int mt = 0; mt < 4; mt++)
#pragma unroll
            for (int nt = 0; nt < 4; nt++) {
                int row = bm + r0 + mt * 16;
                int col = bn + c0 + nt * 8;
                float2 t0 = *(float2*)(C + (size_t)row * N + col);
                float2 t1 = *(float2*)(C + (size_t)(row + 8) * N + col);
                uint32_t hpk, lpk;
                split2(acc[mt][nt][0] + t0.x, acc[mt][nt][1] + t0.y, hpk, lpk);
                *(uint32_t*)(O1 + (size_t)row * N + col) = hpk;
                *(uint32_t*)(O2 + (size_t)row * N + col) = lpk;
                split2(acc[mt][nt][2] + t1.x, acc[mt][nt][3] + t1.y, hpk, lpk);
                *(uint32_t*)(O1 + (size_t)(row + 8) * N + col) = hpk;
                *(uint32_t*)(O2 + (size_t)(row + 8) * N + col) = lpk;
            }
    } else if (EPI == 2) {
#pragma unroll
        for (int mt = 0; mt < 4; mt++)
#pragma unroll
            for (int nt = 0; nt < 4; nt++) {
                int row = bm + r0 + mt * 16;
                int col = bn + c0 + nt * 8;
                float b0 = bias[col], b1 = bias[col + 1];
                uint32_t hpk, lpk;
                split2(acc[mt][nt][0] + b0, acc[mt][nt][1] + b1, hpk, lpk);
                *(uint32_t*)(O1 + (size_t)row * N + col) = hpk;
                *(uint32_t*)(O2 + (size_t)row * N + col) = lpk;
                split2(acc[mt][nt][2] + b0, acc[mt][nt][3] + b1, hpk, lpk);
                *(uint32_t*)(O1 + (size_t)(row + 8) * N + col) = hpk;
                *(uint32_t*)(O2 + (size_t)(row + 8) * N + col) = lpk;
            }
    } else {
        // EPI 1: rope + bf16; pairs (i, i+64) live in this 128-col block (one head).
        float* stile = (float*)smem;   // [128][132]
#pragma unroll
        for (int mt = 0; mt < 4; mt++)
#pragma unroll
            for (int nt = 0; nt < 4; nt++) {
                int rr2 = r0 + mt * 16;
                int cc2 = c0 + nt * 8;
                float b0 = bias[bn + cc2], b1 = bias[bn + cc2 + 1];
                stile[rr2 * 132 + cc2]           = acc[mt][nt][0] + b0;
                stile[rr2 * 132 + cc2 + 1]       = acc[mt][nt][1] + b1;
                stile[(rr2 + 8) * 132 + cc2]     = acc[mt][nt][2] + b0;
                stile[(rr2 + 8) * 132 + cc2 + 1] = acc[mt][nt][3] + b1;
            }
        __syncthreads();
#pragma unroll
        for (int j = 0; j < 32; j++) {
            int idx = tid + 256 * j;
            int row = idx >> 6, i = idx & 63;
            int token = bm + row;
            int pos = token & (SEQ - 1);
            float cw = g_cos[pos * 64 + i], sw = g_sin[pos * 64 + i];
            float x1 = stile[row * 132 + i];
            float x2 = stile[row * 132 + i + 64];
            O1[(size_t)token * N + bn + i]      = __float2bfloat16(x1 * cw - x2 * sw);
            O1[(size_t)token * N + bn + i + 64] = __float2bfloat16(x2 * cw + x1 * sw);
        }
    }
}

// ---------------- fp32 -> bf16 hi/lo split ---------------------------------------
__global__ void split_fp32(const float4* __restrict__ X, __nv_bfloat16* __restrict__ H,
                           __nv_bfloat16* __restrict__ L, int n4)
{
    int i = blockIdx.x * blockDim.x + threadIdx.x;
    if (i >= n4) return;
    float4 v = X[i];
    float vv[4] = {v.x, v.y, v.z, v.w};
    uint32_t hp[2], lp[2];
#pragma unroll
    for (int p = 0; p < 2; p++)
        split2(vv[p * 2 + 0], vv[p * 2 + 1], hp[p], lp[p]);
    *(uint2*)(H + (size_t)i * 4) = make_uint2(hp[0], hp[1]);
    *(uint2*)(L + (size_t)i * 4) = make_uint2(lp[0], lp[1]);
}

// ---------------- W [2048,N] fp32 -> W^T [N,2048] bf16 hi/lo ----------------------
__global__ void transp_split(const float* __restrict__ W, __nv_bfloat16* __restrict__ H,
                             __nv_bfloat16* __restrict__ L, int N)
{
    __shared__ float t[32][33];
    int n0 = blockIdx.x * 32, k0 = blockIdx.y * 32;
    int tx = threadIdx.x, ty = threadIdx.y;
#pragma unroll
    for (int i = 0; i < 32; i += 8)
        t[ty + i][tx] = W[(size_t)(k0 + ty + i) * N + n0 + tx];
    __syncthreads();
#pragma unroll
    for (int i = 0; i < 32; i += 8) {
        float v = t[tx][ty + i];
        __nv_bfloat16 h = __float2bfloat16(v);
        __nv_bfloat16 l = __float2bfloat16(v - __bfloat162float(h));
        size_t o = (size_t)(n0 + ty + i) * GK + k0 + tx;
        H[o] = h; L[o] = l;
    }
}

// ---------------- RoPE cos/sin table (fp64, tiny) ---------------------------------
__global__ void rope_table()
{
    int idx = blockIdx.x * blockDim.x + threadIdx.x;
    if (idx >= SEQ * 64) return;
    int pos = idx >> 6, i = idx & 63;
    double ang = (double)pos * exp(-(double)i * (9.210340371976184 / 64.0));
    g_cos[idx] = (float)cos(ang);
    g_sin[idx] = (float)sin(ang);
}

// ---------------- Flash attention (64-query tile, DB K/V, 2 CTA/SM, warp-skip) ----
#define FSMEM (16384 + 2 * 49152)

__global__ __launch_bounds__(128, 2) void flash_mma(
    const __nv_bfloat16* __restrict__ Q, const __nv_bfloat16* __restrict__ K,
    const __nv_bfloat16* __restrict__ Vh, const __nv_bfloat16* __restrict__ Vl,
    __nv_bfloat16* __restrict__ Oh, __nv_bfloat16* __restrict__ Ol, int qoff)
{
    extern __shared__ __align__(128) char smem[];
    const uint32_t sb = smem_u32(smem);
    const uint32_t sQ = sb;
    const int qb = blockIdx.x + qoff, h = blockIdx.y, b = blockIdx.z;
    const int kvh = h >> 2;
    const int tid = threadIdx.x, lane = tid & 31, w = tid >> 5;
    const int q0 = qb * 64;
    const int l8 = lane & 7, grp = lane >> 3, qd = lane >> 2, ln4 = lane & 3;
    const float scale = 0.08838834764831845f;

#pragma unroll
    for (int i = 0; i < 8; i++) {
        int cid = tid + 128 * i;
        int row = cid >> 4, c = cid & 15;
        uint32_t soff = row * 256 + ((((c ^ row) & 7) | (c & 8)) << 4);
        size_t goff = (size_t)(b * SEQ + q0 + row) * HIDDEN + h * HD + c * 8;
        cpasync16(sQ + soff, Q + goff);
    }
    asm volatile("cp.async.commit_group;" ::: "memory");

    int kstart = q0 - (WINDOW - 1);
    if (kstart < 0) kstart = 0;
    const int kb0 = kstart & ~63;
    const int nblk = (q0 - kb0) / 64 + 1;

    auto load_kv = [&](int kb, int buf) {
        const uint32_t base = sb + 16384 + buf * 49152;
#pragma unroll
        for (int i = 0; i < 8; i++) {
            int cid = tid + 128 * i;
            int row = cid >> 4, c = cid & 15;
            uint32_t soff = row * 256 + ((((c ^ row) & 7) | (c & 8)) << 4);
            size_t goff = (size_t)(b * SEQ + kb + row) * KVD + kvh * HD + c * 8;
            cpasync16(base + soff,         K + goff);
            cpasync16(base + 16384 + soff, Vh + goff);
            cpasync16(base + 32768 + soff, Vl + goff);
        }
        asm volatile("cp.async.commit_group;" ::: "memory");
    };

    load_kv(kb0, 0);

    asm volatile("cp.async.wait_group 1;" ::: "memory");
    __syncthreads();
    uint32_t qhf[8][4];
#pragma unroll
    for (int kt = 0; kt < 8; kt++) {
        int row = w * 16 + l8 + ((grp & 1) << 3);
        int ch  = 2 * kt + (grp >> 1);
        uint32_t off = row * 256 + ((((ch ^ row) & 7) | (ch & 8)) << 4);
        ldmx4(qhf[kt], sQ + off);
    }

    float of[16][4];
#pragma unroll
    for (int i = 0; i < 16; i++)
#pragma unroll
        for (int e = 0; e < 4; e++) of[i][e] = 0.f;
    float m0 = -1e30f, m1 = -1e30f, l0 = 0.f, l1 = 0.f;
    const int qw    = q0 + w * 16;
    const int qpos0 = qw + qd;
    const int qpos1 = qpos0 + 8;

    for (int i = 0; i < nblk; i++) {
        const int kb  = kb0 + i * 64;
        const int buf = i & 1;
        __syncthreads();
        if (i + 1 < nblk) {
            load_kv(kb + 64, 1 - buf);
            asm volatile("cp.async.wait_group 1;" ::: "memory");
        } else {
            asm volatile("cp.async.wait_group 0;" ::: "memory");
        }
        __syncthreads();

        if (kb + 63 + WINDOW <= qw) continue;

        const uint32_t kvb = sb + 16384 + buf * 49152;
        const uint32_t sK = kvb, sVh = kvb + 16384, sVl = kvb + 32768;

        float s[8][4];
#pragma unroll
        for (int nt = 0; nt < 8; nt++)
#pragma unroll
            for (int e = 0; e < 4; e++) s[nt][e] = 0.f;
#pragma unroll
        for (int kt = 0; kt < 8; kt++) {
            uint32_t bh[4][4];
#pragma unroll
            for (int kg = 0; kg < 4; kg++) {
                int key = kg * 16 + l8 + ((grp >> 1) << 3);
                int ch  = 2 * kt + (grp & 1);
                uint32_t off = key * 256 + ((((ch ^ key) & 7) | (ch & 8)) << 4);
                ldmx4(bh[kg], sK + off);
            }
#pragma unroll
            for (int nt = 0; nt < 8; nt++)
                mma16816(s[nt], qhf[kt], &bh[nt >> 1][(nt & 1) * 2]);
        }

        float bmax0 = -1e30f, bmax1 = -1e30f;
#pragma unroll
        for (int nt = 0; nt < 8; nt++) {
            int colb = kb + nt * 8 + ln4 * 2;
#pragma unroll
            for (int e = 0; e < 4; e++) {
                int col = colb + (e & 1);
                int qp  = (e < 2) ? qpos0 : qpos1;
                bool ok = (col <= qp) && (col > qp - WINDOW);
                s[nt][e] = ok ? s[nt][e] * scale : -1e30f;
            }
            bmax0 = fmaxf(bmax0, fmaxf(s[nt][0], s[nt][1]));
            bmax1 = fmaxf(bmax1, fmaxf(s[nt][2], s[nt][3]));
        }
        bmax0 = fmaxf(bmax0, __shfl_xor_sync(0xffffffffu, bmax0, 1));
        bmax0 = fmaxf(bmax0, __shfl_xor_sync(0xffffffffu, bmax0, 2));
        bmax1 = fmaxf(bmax1, __shfl_xor_sync(0xffffffffu, bmax1, 1));
        bmax1 = fmaxf(bmax1, __shfl_xor_sync(0xffffffffu, bmax1, 2));
        float mn0 = fmaxf(m0, bmax0), mn1 = fmaxf(m1, bmax1);
        bool dead0 = mn0 < -1e29f, dead1 = mn1 < -1e29f;
        float corr0 = dead0 ? 1.f : __expf(m0 - mn0);
        float corr1 = dead1 ? 1.f : __expf(m1 - mn1);
        float rs0 = 0.f, rs1 = 0.f;
#pragma unroll
        for (int nt = 0; nt < 8; nt++) {
            s[nt][0] = dead0 ? 0.f : __expf(s[nt][0] - mn0);
            s[nt][1] = dead0 ? 0.f : __expf(s[nt][1] - mn0);
            s[nt][2] = dead1 ? 0.f : __expf(s[nt][2] - mn1);
            s[nt][3] = dead1 ? 0.f : __expf(s[nt][3] - mn1);
            rs0 += s[nt][0] + s[nt][1];
            rs1 += s[nt][2] + s[nt][3];
        }
        rs0 += __shfl_xor_sync(0xffffffffu, rs0, 1);
        rs0 += __shfl_xor_sync(0xffffffffu, rs0, 2);
        rs1 += __shfl_xor_sync(0xffffffffu, rs1, 1);
        rs1 += __shfl_xor_sync(0xffffffffu, rs1, 2);
        l0 = l0 * corr0 + rs0;
        l1 = l1 * corr1 + rs1;
        m0 = mn0; m1 = mn1;
#pragma unroll
        for (int nt = 0; nt < 16; nt++) {
            of[nt][0] *= corr0; of[nt][1] *= corr0;
            of[nt][2] *= corr1; of[nt][3] *= corr1;
        }

#pragma unroll
        for (int kt2 = 0; kt2 < 4; kt2++) {
            uint32_t pah[4], pal[4];
            split2(s[2 * kt2][0],     s[2 * kt2][1],     pah[0], pal[0]);
            split2(s[2 * kt2][2],     s[2 * kt2][3],     pah[1], pal[1]);
            split2(s[2 * kt2 + 1][0], s[2 * kt2 + 1][1], pah[2], pal[2]);
            split2(s[2 * kt2 + 1][2], s[2 * kt2 + 1][3], pah[3], pal[3]);
#pragma unroll
            for (int ntp = 0; ntp < 8; ntp++) {
                uint32_t vhf[4], vlf[4];
                int key = 16 * kt2 + l8 + ((grp & 1) << 3);
                int ch  = 2 * ntp + (grp >> 1);
                uint32_t off = key * 256 + ((((ch ^ key) & 7) | (ch & 8)) << 4);
                ldmx4t(vhf, sVh + off);
                ldmx4t(vlf, sVl + off);
                mma16816(of[2 * ntp],     pah, &vhf[0]);
                mma16816(of[2 * ntp],     pah, &vlf[0]);
                mma16816(of[2 * ntp],     pal, &vhf[0]);
                mma16816(of[2 * ntp + 1], pah, &vhf[2]);
                mma16816(of[2 * ntp + 1], pah, &vlf[2]);
                mma16816(of[2 * ntp + 1], pal, &vhf[2]);
            }
        }
    }

    float il0 = 1.f / l0, il1 = 1.f / l1;
    const int tok0 = b * SEQ + q0 + w * 16 + qd;
#pragma unroll
    for (int nt = 0; nt < 16; nt++) {
        int col = h * HD + nt * 8 + ln4 * 2;
        uint32_t hpk, lpk;
        split2(of[nt][0] * il0, of[nt][1] * il0, hpk, lpk);
        *(uint32_t*)(Oh + (size_t)tok0 * HIDDEN + col) = hpk;
        *(uint32_t*)(Ol + (size_t)tok0 * HIDDEN + col) = lpk;
        split2(of[nt][2] * il1, of[nt][3] * il1, hpk, lpk);
        *(uint32_t*)(Oh + (size_t)(tok0 + 8) * HIDDEN + col) = hpk;
        *(uint32_t*)(Ol + (size_t)(tok0 + 8) * HIDDEN + col) = lpk;
    }
}

// ---------------- launch ----------------------------------------------------------
extern "C" void kernel_launch(void* const* d_in, const int* in_sizes, int n_in,
                              void* d_out, int out_size)
{
    const float* hs = (const float*)d_in[0];
    const float* Wq = (const float*)d_in[2];
    const float* bq = (const float*)d_in[3];
    const float* Wk = (const float*)d_in[4];
    const float* bk = (const float*)d_in[5];
    const float* Wv = (const float*)d_in[6];
    const float* bv = (const float*)d_in[7];
    const float* Wo = (const float*)d_in[8];
    float* out = (float*)d_out;

    void *pxh, *pxl, *pqb, *pkb, *pvh, *pvl, *ptmp;
    void *pwqh, *pwql, *pwkh, *pwkl, *pwvh, *pwvl, *pwoh, *pwol;
    cudaGetSymbolAddress(&pxh, g_xh);
    cudaGetSymbolAddress(&pxl, g_xl);
    cudaGetSymbolAddress(&pqb, g_qb);
    cudaGetSymbolAddress(&pkb, g_kb);
    cudaGetSymbolAddress(&pvh, g_vh);
    cudaGetSymbolAddress(&pvl, g_vl);
    cudaGetSymbolAddress(&ptmp, g_tmp);
    cudaGetSymbolAddress(&pwqh, g_wqh);
    cudaGetSymbolAddress(&pwql, g_wql);
    cudaGetSymbolAddress(&pwkh, g_wkh);
    cudaGetSymbolAddress(&pwkl, g_wkl);
    cudaGetSymbolAddress(&pwvh, g_wvh);
    cudaGetSymbolAddress(&pwvl, g_wvl);
    cudaGetSymbolAddress(&pwoh, g_woh);
    cudaGetSymbolAddress(&pwol, g_wol);
    __nv_bfloat16* xh = (__nv_bfloat16*)pxh;
    __nv_bfloat16* xl = (__nv_bfloat16*)pxl;
    float* vtmp = (float*)ptmp;

    static cudaStream_t s1 = nullptr, s2 = nullptr;
    static cudaEvent_t ev0 = nullptr, evA = nullptr, evRT = nullptr, evWq = nullptr,
                       evK = nullptr, evV = nullptr, evWo = nullptr,
                       evQA = nullptr, evOA = nullptr;
    if (!s1) {
        cudaStreamCreateWithFlags(&s1, cudaStreamNonBlocking);
        cudaStreamCreateWithFlags(&s2, cudaStreamNonBlocking);
        cudaEventCreateWithFlags(&ev0, cudaEventDisableTiming);
        cudaEventCreateWithFlags(&evA, cudaEventDisableTiming);
        cudaEventCreateWithFlags(&evRT, cudaEventDisableTiming);
        cudaEventCreateWithFlags(&evWq, cudaEventDisableTiming);
        cudaEventCreateWithFlags(&evK, cudaEventDisableTiming);
        cudaEventCreateWithFlags(&evV, cudaEventDisableTiming);
        cudaEventCreateWithFlags(&evWo, cudaEventDisableTiming);
        cudaEventCreateWithFlags(&evQA, cudaEventDisableTiming);
        cudaEventCreateWithFlags(&evOA, cudaEventDisableTiming);
    }

    const int SM1 = 3 * 2 * 16384;   // 96KB (NT=2, 3 stages)
    const int SMH = 2 * 3 * 16384;   // 96KB (NT=3, 2 stages)
    cudaFuncSetAttribute((const void*)gemm_mma<2, 1, 2, 3>, cudaFuncAttributeMaxDynamicSharedMemorySize, SM1);
    cudaFuncSetAttribute((const void*)gemm_mma<3, 0, 2, 2>, cudaFuncAttributeMaxDynamicSharedMemorySize, SMH);
    cudaFuncSetAttribute((const void*)gemm_mma<2, 3, 2, 3>, cudaFuncAttributeMaxDynamicSharedMemorySize, SM1);
    cudaFuncSetAttribute((const void*)gemm_mma<2, 4, 2, 3>, cudaFuncAttributeMaxDynamicSharedMemorySize, SM1);
    cudaFuncSetAttribute((const void*)flash_mma, cudaFuncAttributeMaxDynamicSharedMemorySize, FSMEM);

    const int n4h = MTOK * GK / 4;
    dim3 tb(32, 8);

    // fork
    cudaEventRecord(ev0, 0);
    cudaStreamWaitEvent(s1, ev0, 0);
    cudaStreamWaitEvent(s2, ev0, 0);

    // s0: activation split only (minimal serial prefix)
    split_fp32<<<(n4h + 255) / 256, 256>>>((const float4*)hs, xh, xl, n4h);
    cudaEventRecord(evA, 0);

    // s1: rope table, K path
    rope_table<<<(SEQ * 64 + 255) / 256, 256, 0, s1>>>();
    cudaEventRecord(evRT, s1);
    transp_split<<<dim3(KVD / 32, GK / 32), tb, 0, s1>>>(Wk, (__nv_bfloat16*)pwkh, (__nv_bfloat16*)pwkl, KVD);
    cudaStreamWaitEvent(s1, evA, 0);
    gemm_mma<2, 1, 2, 3><<<dim3(KVD / 128, MTOK / 128), 256, SM1, s1>>>(
        xh, nullptr, (__nv_bfloat16*)pwkh, nullptr, bk, nullptr,
        (__nv_bfloat16*)pkb, nullptr, KVD, -1);
    cudaEventRecord(evK, s1);

    // s2: Wq transpose first (unblocks Q-projA ASAP), then V path, then Wo transpose
    transp_split<<<dim3(HIDDEN / 32, GK / 32), tb, 0, s2>>>(Wq, (__nv_bfloat16*)pwqh, (__nv_bfloat16*)pwql, HIDDEN);
    cudaEventRecord(evWq, s2);
    transp_split<<<dim3(KVD / 32, GK / 32), tb, 0, s2>>>(Wv, (__nv_bfloat16*)pwvh, (__nv_bfloat16*)pwvl, KVD);
    cudaStreamWaitEvent(s2, evA, 0);
    gemm_mma<3, 0, 2, 2><<<dim3(KVD / 128, MTOK / 128), 256, SMH, s2>>>(
        xh, xl, (__nv_bfloat16*)pwvh, nullptr, bv, vtmp,
        nullptr, nullptr, KVD, -1);
    gemm_mma<2, 4, 2, 3><<<dim3(KVD / 128, MTOK / 128), 256, SM1, s2>>>(
        xh, nullptr, (__nv_bfloat16*)pwvl, nullptr, nullptr, vtmp,
        (__nv_bfloat16*)pvh, (__nv_bfloat16*)pvl, KVD, -1);
    cudaEventRecord(evV, s2);
    transp_split<<<dim3(HIDDEN / 32, GK / 32), tb, 0, s2>>>(Wo, (__nv_bfloat16*)pwoh, (__nv_bfloat16*)pwol, HIDDEN);
    cudaEventRecord(evWo, s2);

    // s0: Q path, token-half A then B (Wq transpose done on s2)
    cudaStreamWaitEvent(0, evWq, 0);
    cudaStreamWaitEvent(0, evRT, 0);
    gemm_mma<2, 1, 2, 3><<<dim3(HIDDEN / 128, 16), 256, SM1>>>(
        xh, nullptr, (__nv_bfloat16*)pwqh, nullptr, bq, nullptr,
        (__nv_bfloat16*)pqb, nullptr, HIDDEN, 0);
    cudaEventRecord(evQA, 0);
    gemm_mma<2, 1, 2, 3><<<dim3(HIDDEN / 128, 16), 256, SM1>>>(
        xh, nullptr, (__nv_bfloat16*)pwqh, nullptr, bq, nullptr,
        (__nv_bfloat16*)pqb, nullptr, HIDDEN, 1);

    // s1: flashA || Q-projB, then O-projA (two 2-CTA/SM kernels)
    cudaStreamWaitEvent(s1, evQA, 0);
    cudaStreamWaitEvent(s1, evV, 0);
    flash_mma<<<dim3(16, NH, BATCH), 128, FSMEM, s1>>>(
        (__nv_bfloat16*)pqb, (__nv_bfloat16*)pkb,
        (__nv_bfloat16*)pvh, (__nv_bfloat16*)pvl, xh, xl, 0);
    cudaStreamWaitEvent(s1, evWo, 0);
    gemm_mma<3, 0, 2, 2><<<dim3(HIDDEN / 128, 16), 256, SMH, s1>>>(
        xh, xl, (__nv_bfloat16*)pwoh, nullptr, nullptr, out,
        nullptr, nullptr, HIDDEN, 0);
    gemm_mma<2, 3, 2, 3><<<dim3(HIDDEN / 128, 16), 256, SM1, s1>>>(
        xh, nullptr, (__nv_bfloat16*)pwol, nullptr, nullptr, out,
        nullptr, nullptr, HIDDEN, 0);
    cudaEventRecord(evOA, s1);

    // s0: flashB, then O-projB
    cudaStreamWaitEvent(0, evK, 0);
    cudaStreamWaitEvent(0, evV, 0);
    flash_mma<<<dim3(16, NH, BATCH), 128, FSMEM>>>(
        (__nv_bfloat16*)pqb, (__nv_bfloat16*)pkb,
        (__nv_bfloat16*)pvh, (__nv_bfloat16*)pvl, xh, xl, 16);
    cudaStreamWaitEvent(0, evWo, 0);
    gemm_mma<3, 0, 2, 2><<<dim3(HIDDEN / 128, 16), 256, SMH>>>(
        xh, xl, (__nv_bfloat16*)pwoh, nullptr, nullptr, out,
        nullptr, nullptr, HIDDEN, 1);
    gemm_mma<2, 3, 2, 3><<<dim3(HIDDEN / 128, 16), 256, SM1>>>(
        xh, nullptr, (__nv_bfloat16*)pwol, nullptr, nullptr, out,
        nullptr, nullptr, HIDDEN, 1);

    // join s1 back to the origin stream
    cudaStreamWaitEvent(0, evOA, 0);
}

// round 17
// speedup vs baseline: 1.0285x; 1.0285x over previous
#include <cuda_runtime.h>
#include <cuda_bf16.h>
#include <math.h>
#include <cstdint>

#define HIDDEN 2048
#define NH 16
#define NKV 4
#define HD 128
#define KVD 512
#define WINDOW 1024
#define BATCH 2
#define SEQ 2048
#define MTOK 4096
#define GK 2048

// ---------------- scratch (static device globals; no allocation) ----------------
__device__ __nv_bfloat16 g_xh[MTOK * GK], g_xl[MTOK * GK];
__device__ __nv_bfloat16 g_qb[MTOK * HIDDEN];
__device__ __nv_bfloat16 g_kb[MTOK * KVD];
__device__ __nv_bfloat16 g_vh[MTOK * KVD], g_vl[MTOK * KVD];
__device__ float g_tmp[MTOK * KVD];   // V-proj partial (fp32)
__device__ __nv_bfloat16 g_wqh[HIDDEN * GK], g_wql[HIDDEN * GK];
__device__ __nv_bfloat16 g_wkh[KVD * GK],    g_wkl[KVD * GK];
__device__ __nv_bfloat16 g_wvh[KVD * GK],    g_wvl[KVD * GK];
__device__ __nv_bfloat16 g_woh[HIDDEN * GK], g_wol[HIDDEN * GK];
__device__ float g_cos[SEQ * 64], g_sin[SEQ * 64];

// ---------------- helpers --------------------------------------------------------
__device__ __forceinline__ uint32_t smem_u32(const void* p) {
    uint32_t a;
    asm("{ .reg .u64 t; cvta.to.shared.u64 t, %1; cvt.u32.u64 %0, t; }" : "=r"(a) : "l"(p));
    return a;
}
__device__ __forceinline__ void ldmx4(uint32_t* r, uint32_t addr) {
    asm volatile("ldmatrix.sync.aligned.m8n8.x4.shared.b16 {%0,%1,%2,%3}, [%4];"
                 : "=r"(r[0]), "=r"(r[1]), "=r"(r[2]), "=r"(r[3]) : "r"(addr));
}
__device__ __forceinline__ void ldmx4t(uint32_t* r, uint32_t addr) {
    asm volatile("ldmatrix.sync.aligned.m8n8.x4.trans.shared.b16 {%0,%1,%2,%3}, [%4];"
                 : "=r"(r[0]), "=r"(r[1]), "=r"(r[2]), "=r"(r[3]) : "r"(addr));
}
__device__ __forceinline__ void mma16816(float* d, const uint32_t* a, const uint32_t* b) {
    asm volatile(
        "mma.sync.aligned.m16n8k16.row.col.f32.bf16.bf16.f32 "
        "{%0,%1,%2,%3}, {%4,%5,%6,%7}, {%8,%9}, {%0,%1,%2,%3};"
        : "+f"(d[0]), "+f"(d[1]), "+f"(d[2]), "+f"(d[3])
        : "r"(a[0]), "r"(a[1]), "r"(a[2]), "r"(a[3]), "r"(b[0]), "r"(b[1]));
}
__device__ __forceinline__ void split2(float a, float b, uint32_t& hpk, uint32_t& lpk) {
    asm("cvt.rn.bf16x2.f32 %0, %1, %2;" : "=r"(hpk) : "f"(b), "f"(a));
    float fa = __uint_as_float(hpk << 16);
    float fb = __uint_as_float(hpk & 0xffff0000u);
    float ra = a - fa, rb = b - fb;
    asm("cvt.rn.bf16x2.f32 %0, %1, %2;" : "=r"(lpk) : "f"(rb), "f"(ra));
}
__device__ __forceinline__ void cpasync16(uint32_t dst, const void* src) {
    asm volatile("cp.async.cg.shared.global [%0], [%1], 16;" :: "r"(dst), "l"(src) : "memory");
}

// ---------------- GEMM via mma.sync ------------------------------------------------
// NT staged tensors: 2={Ah,Bh} 1 pass; 3={Ah,Al,Bh} 2 passes; 4={Ah,Al,Bh,Bl} 3 passes.
// EPI: 0 fp32 store (+bias), 1 rope+bf16, 2 split store (+bias), 3 fp32 accumulate-add,
//      4 read fp32 C + add + split store.
// NST: pipeline stages. msplit: -1 full grid; 0/1 token-half (grid.y = 16).
template <int NT, int EPI, int MINB, int NST>
__global__ __launch_bounds__(256, MINB) void gemm_mma(
    const __nv_bfloat16* __restrict__ Ah, const __nv_bfloat16* __restrict__ Al,
    const __nv_bfloat16* __restrict__ Bh, const __nv_bfloat16* __restrict__ Bl,
    const float* __restrict__ bias, float* __restrict__ C,
    __nv_bfloat16* __restrict__ O1, __nv_bfloat16* __restrict__ O2, int N, int msplit)
{
    extern __shared__ __align__(128) char smem[];
    const uint32_t sb = smem_u32(smem);
    const int tid  = threadIdx.x;
    const int lane = tid & 31;
    const int wid  = tid >> 5;
    const int wm   = wid >> 2;
    const int wn   = wid & 3;
    const int bn   = blockIdx.x * 128;
    int mb = blockIdx.y;
    if (msplit >= 0) mb = ((blockIdx.y >> 3) << 4) + msplit * 8 + (blockIdx.y & 7);
    const int bm   = mb * 128;

    const int STAGE = NT * 16384;
    const int BHOFF = (NT == 2) ? 16384 : 32768;

    const __nv_bfloat16* srcs[NT];
    if (NT == 2) {
        srcs[0] = Ah + (size_t)bm * GK;
        srcs[1] = Bh + (size_t)bn * GK;
    } else if (NT == 3) {
        srcs[0] = Ah + (size_t)bm * GK;
        srcs[1] = Al + (size_t)bm * GK;
        srcs[2] = Bh + (size_t)bn * GK;
    } else {
        srcs[0] = Ah + (size_t)bm * GK;
        srcs[1] = Al + (size_t)bm * GK;
        srcs[2] = Bh + (size_t)bn * GK;
        srcs[3] = Bl + (size_t)bn * GK;
    }
    const int rr = tid >> 3, cc = tid & 7;

    const int idx8   = lane & 7;
    const int a_moff = ((lane >> 3) & 1) * 8;
    const int a_coff = lane >> 4;
    const int b_noff = (lane >> 4) * 8;
    const int b_coff = (lane >> 3) & 1;

    float acc[4][4][4];
#pragma unroll
    for (int i = 0; i < 4; i++)
#pragma unroll
        for (int j = 0; j < 4; j++)
#pragma unroll
            for (int e = 0; e < 4; e++) acc[i][j][e] = 0.f;

    auto issue = [&](int c, int buf) {
        const int k0 = c * 64;
        const uint32_t st = sb + buf * STAGE;
#pragma unroll
        for (int t = 0; t < NT; t++) {
            const __nv_bfloat16* bp = srcs[t] + k0 + cc * 8;
#pragma unroll
            for (int j = 0; j < 4; j++) {
                int r = rr + 32 * j;
                int byte = r * 128 + cc * 16;
                uint32_t dst = st + t * 16384 + (byte ^ ((byte >> 3) & 0x70));
                cpasync16(dst, bp + (size_t)r * GK);
            }
        }
        asm volatile("cp.async.commit_group;" ::: "memory");
    };

#pragma unroll
    for (int p = 0; p < NST; p++) issue(p, p);

    for (int c = 0; c < 32; c++) {
        if (NST == 3) {
            if (c <= 29)      asm volatile("cp.async.wait_group 2;" ::: "memory");
            else if (c == 30) asm volatile("cp.async.wait_group 1;" ::: "memory");
            else              asm volatile("cp.async.wait_group 0;" ::: "memory");
        } else {
            if (c <= 30)      asm volatile("cp.async.wait_group 1;" ::: "memory");
            else              asm volatile("cp.async.wait_group 0;" ::: "memory");
        }
        __syncthreads();
        const uint32_t st = sb + (c % NST) * STAGE;

#pragma unroll
        for (int ks = 0; ks < 4; ks++) {
            uint32_t ah[4][4], al[4][4], bh[2][4], bl[2][4];
            const int chA = ks * 2 + a_coff;
            const int chB = ks * 2 + b_coff;
#pragma unroll
            for (int mt = 0; mt < 4; mt++) {
                int row = wm * 64 + mt * 16 + a_moff + idx8;
                uint32_t off = row * 128 + ((chA ^ (row & 7)) << 4);
                ldmx4(ah[mt], st + off);
                if (NT >= 3) ldmx4(al[mt], st + 16384 + off);
            }
#pragma unroll
            for (int h = 0; h < 2; h++) {
                int row = wn * 32 + h * 16 + b_noff + idx8;
                uint32_t off = row * 128 + ((chB ^ (row & 7)) << 4);
                ldmx4(bh[h], st + BHOFF + off);
                if (NT == 4) ldmx4(bl[h], st + 49152 + off);
            }
#pragma unroll
            for (int mt = 0; mt < 4; mt++)
#pragma unroll
                for (int nt = 0; nt < 4; nt++) {
                    const uint32_t* ph = &bh[nt >> 1][(nt & 1) * 2];
                    mma16816(acc[mt][nt], ah[mt], ph);
                    if (NT >= 3) mma16816(acc[mt][nt], al[mt], ph);
                    if (NT == 4) {
                        const uint32_t* pl = &bl[nt >> 1][(nt & 1) * 2];
                        mma16816(acc[mt][nt], ah[mt], pl);
                    }
                }
        }
        __syncthreads();
        if (c + NST < 32) issue(c + NST, (c + NST) % NST);
    }

    const int r0   = wm * 64 + (lane >> 2);
    const int c0   = wn * 32 + (lane & 3) * 2;

    if (EPI == 0) {
#pragma unroll
        for (int mt = 0; mt < 4; mt++)
#pragma unroll
            for (int nt = 0; nt < 4; nt++) {
                int row = bm + r0 + mt * 16;
                int col = bn + c0 + nt * 8;
                float b0 = 0.f, b1 = 0.f;
                if (bias) { b0 = bias[col]; b1 = bias[col + 1]; }
                *(float2*)(C + (size_t)row * N + col)       = make_float2(acc[mt][nt][0] + b0, acc[mt][nt][1] + b1);
                *(float2*)(C + (size_t)(row + 8) * N + col) = make_float2(acc[mt][nt][2] + b0, acc[mt][nt][3] + b1);
            }
    } else if (EPI == 3) {
#pragma unroll
        for (int mt = 0; mt < 4; mt++)
#pragma unroll
            for (int nt = 0; nt < 4; nt++) {
                int row = bm + r0 + mt * 16;
                int col = bn + c0 + nt * 8;
                float2* p0 = (float2*)(C + (size_t)row * N + col);
                float2* p1 = (float2*)(C + (size_t)(row + 8) * N + col);
                float2 v0 = *p0, v1 = *p1;
                v0.x += acc[mt][nt][0]; v0.y += acc[mt][nt][1];
                v1.x += acc[mt][nt][2]; v1.y += acc[mt][nt][3];
                *p0 = v0; *p1 = v1;
            }
    } else if (EPI == 4) {
#pragma unroll
        for (int mt = 0; mt < 4; mt++)
#pragma unroll
            for (int nt = 0; nt < 4; nt++) {
                int row = bm + r0 + mt * 16;
                int col = bn + c0 + nt * 8;
                float2 t0 = *(float2*)(C + (size_t)row * N + col);
                float2 t1 = *(float2*)(C + (size_t)(row + 8) * N + col);
                uint32_t hpk, lpk;
                split2(acc[mt][nt][0] + t0.x, acc[mt][nt][1] + t0.y, hpk, lpk);
                *(uint32_t*)(O1 + (size_t)row * N + col) = hpk;
                *(uint32_t*)(O2 + (size_t)row * N + col) = lpk;
                split2(acc[mt][nt][2] + t1.x, acc[mt][nt][3] + t1.y, hpk, lpk);
                *(uint32_t*)(O1 + (size_t)(row + 8) * N + col) = hpk;
                *(uint32_t*)(O2 + (size_t)(row + 8) * N + col) = lpk;
            }
    } else if (EPI == 2) {
#pragma unroll
        for (int mt = 0; mt < 4; mt++)
#pragma unroll
            for (int nt = 0; nt < 4; nt++) {
                int row = bm + r0 + mt * 16;
                int col = bn + c0 + nt * 8;
                float b0 = bias[col], b1 = bias[col + 1];
                uint32_t hpk, lpk;
                split2(acc[mt][nt][0] + b0, acc[mt][nt][1] + b1, hpk, lpk);
                *(uint32_t*)(O1 + (size_t)row * N + col) = hpk;
                *(uint32_t*)(O2 + (size_t)row * N + col) = lpk;
                split2(acc[mt][nt][2] + b0, acc[mt][nt][3] + b1, hpk, lpk);
                *(uint32_t*)(O1 + (size_t)(row + 8) * N + col) = hpk;
                *(uint32_t*)(O2 + (size_t)(row + 8) * N + col) = lpk;
            }
    } else {
        // EPI 1: rope + bf16; pairs (i, i+64) live in this 128-col block (one head).
        float* stile = (float*)smem;   // [128][132]
#pragma unroll
        for (int mt = 0; mt < 4; mt++)
#pragma unroll
            for (int nt = 0; nt < 4; nt++) {
                int rr2 = r0 + mt * 16;
                int cc2 = c0 + nt * 8;
                float b0 = bias[bn + cc2], b1 = bias[bn + cc2 + 1];
                stile[rr2 * 132 + cc2]           = acc[mt][nt][0] + b0;
                stile[rr2 * 132 + cc2 + 1]       = acc[mt][nt][1] + b1;
                stile[(rr2 + 8) * 132 + cc2]     = acc[mt][nt][2] + b0;
                stile[(rr2 + 8) * 132 + cc2 + 1] = acc[mt][nt][3] + b1;
            }
        __syncthreads();
#pragma unroll
        for (int j = 0; j < 32; j++) {
            int idx = tid + 256 * j;
            int row = idx >> 6, i = idx & 63;
            int token = bm + row;
            int pos = token & (SEQ - 1);
            float cw = g_cos[pos * 64 + i], sw = g_sin[pos * 64 + i];
            float x1 = stile[row * 132 + i];
            float x2 = stile[row * 132 + i + 64];
            O1[(size_t)token * N + bn + i]      = __float2bfloat16(x1 * cw - x2 * sw);
            O1[(size_t)token * N + bn + i + 64] = __float2bfloat16(x2 * cw + x1 * sw);
        }
    }
}

// ---------------- fp32 -> bf16 hi/lo split ---------------------------------------
__global__ void split_fp32(const float4* __restrict__ X, __nv_bfloat16* __restrict__ H,
                           __nv_bfloat16* __restrict__ L, int n4)
{
    int i = blockIdx.x * blockDim.x + threadIdx.x;
    if (i >= n4) return;
    float4 v = X[i];
    float vv[4] = {v.x, v.y, v.z, v.w};
    uint32_t hp[2], lp[2];
#pragma unroll
    for (int p = 0; p < 2; p++)
        split2(vv[p * 2 + 0], vv[p * 2 + 1], hp[p], lp[p]);
    *(uint2*)(H + (size_t)i * 4) = make_uint2(hp[0], hp[1]);
    *(uint2*)(L + (size_t)i * 4) = make_uint2(lp[0], lp[1]);
}

// ---------------- W [2048,N] fp32 -> W^T [N,2048] bf16 hi/lo ----------------------
__global__ void transp_split(const float* __restrict__ W, __nv_bfloat16* __restrict__ H,
                             __nv_bfloat16* __restrict__ L, int N)
{
    __shared__ float t[32][33];
    int n0 = blockIdx.x * 32, k0 = blockIdx.y * 32;
    int tx = threadIdx.x, ty = threadIdx.y;
#pragma unroll
    for (int i = 0; i < 32; i += 8)
        t[ty + i][tx] = W[(size_t)(k0 + ty + i) * N + n0 + tx];
    __syncthreads();
#pragma unroll
    for (int i = 0; i < 32; i += 8) {
        float v = t[tx][ty + i];
        __nv_bfloat16 h = __float2bfloat16(v);
        __nv_bfloat16 l = __float2bfloat16(v - __bfloat162float(h));
        size_t o = (size_t)(n0 + ty + i) * GK + k0 + tx;
        H[o] = h; L[o] = l;
    }
}

// ---------------- RoPE cos/sin table (fp64, tiny) ---------------------------------
__global__ void rope_table()
{
    int idx = blockIdx.x * blockDim.x + threadIdx.x;
    if (idx >= SEQ * 64) return;
    int pos = idx >> 6, i = idx & 63;
    double ang = (double)pos * exp(-(double)i * (9.210340371976184 / 64.0));
    g_cos[idx] = (float)cos(ang);
    g_sin[idx] = (float)sin(ang);
}

// ---------------- Flash attention (64-query tile, DB K/V, 2 CTA/SM, warp-skip,
//                  interior-block fast path) ---------------------------------------
#define FSMEM (16384 + 2 * 49152)

__global__ __launch_bounds__(128, 2) void flash_mma(
    const __nv_bfloat16* __restrict__ Q, const __nv_bfloat16* __restrict__ K,
    const __nv_bfloat16* __restrict__ Vh, const __nv_bfloat16* __restrict__ Vl,
    __nv_bfloat16* __restrict__ Oh, __nv_bfloat16* __restrict__ Ol, int qoff)
{
    extern __shared__ __align__(128) char smem[];
    const uint32_t sb = smem_u32(smem);
    const uint32_t sQ = sb;
    const int qb = blockIdx.x + qoff, h = blockIdx.y, b = blockIdx.z;
    const int kvh = h >> 2;
    const int tid = threadIdx.x, lane = tid & 31, w = tid >> 5;
    const int q0 = qb * 64;
    const int l8 = lane & 7, grp = lane >> 3, qd = lane >> 2, ln4 = lane & 3;
    const float scale = 0.08838834764831845f;

#pragma unroll
    for (int i = 0; i < 8; i++) {
        int cid = tid + 128 * i;
        int row = cid >> 4, c = cid & 15;
        uint32_t soff = row * 256 + ((((c ^ row) & 7) | (c & 8)) << 4);
        size_t goff = (size_t)(b * SEQ + q0 + row) * HIDDEN + h * HD + c * 8;
        cpasync16(sQ + soff, Q + goff);
    }
    asm volatile("cp.async.commit_group;" ::: "memory");

    int kstart = q0 - (WINDOW - 1);
    if (kstart < 0) kstart = 0;
    const int kb0 = kstart & ~63;
    const int nblk = (q0 - kb0) / 64 + 1;

    auto load_kv = [&](int kb, int buf) {
        const uint32_t base = sb + 16384 + buf * 49152;
#pragma unroll
        for (int i = 0; i < 8; i++) {
            int cid = tid + 128 * i;
            int row = cid >> 4, c = cid & 15;
            uint32_t soff = row * 256 + ((((c ^ row) & 7) | (c & 8)) << 4);
            size_t goff = (size_t)(b * SEQ + kb + row) * KVD + kvh * HD + c * 8;
            cpasync16(base + soff,         K + goff);
            cpasync16(base + 16384 + soff, Vh + goff);
            cpasync16(base + 32768 + soff, Vl + goff);
        }
        asm volatile("cp.async.commit_group;" ::: "memory");
    };

    load_kv(kb0, 0);

    asm volatile("cp.async.wait_group 1;" ::: "memory");
    __syncthreads();
    uint32_t qhf[8][4];
#pragma unroll
    for (int kt = 0; kt < 8; kt++) {
        int row = w * 16 + l8 + ((grp & 1) << 3);
        int ch  = 2 * kt + (grp >> 1);
        uint32_t off = row * 256 + ((((ch ^ row) & 7) | (ch & 8)) << 4);
        ldmx4(qhf[kt], sQ + off);
    }

    float of[16][4];
#pragma unroll
    for (int i = 0; i < 16; i++)
#pragma unroll
        for (int e = 0; e < 4; e++) of[i][e] = 0.f;
    float m0 = -1e30f, m1 = -1e30f, l0 = 0.f, l1 = 0.f;
    const int qw    = q0 + w * 16;
    const int qpos0 = qw + qd;
    const int qpos1 = qpos0 + 8;

    for (int i = 0; i < nblk; i++) {
        const int kb  = kb0 + i * 64;
        const int buf = i & 1;
        __syncthreads();
        if (i + 1 < nblk) {
            load_kv(kb + 64, 1 - buf);
            asm volatile("cp.async.wait_group 1;" ::: "memory");
        } else {
            asm volatile("cp.async.wait_group 0;" ::: "memory");
        }
        __syncthreads();

        if (kb + 63 + WINDOW <= qw) continue;   // dead block for all 16 rows

        const uint32_t kvb = sb + 16384 + buf * 49152;
        const uint32_t sK = kvb, sVh = kvb + 16384, sVl = kvb + 32768;

        float s[8][4];
#pragma unroll
        for (int nt = 0; nt < 8; nt++)
#pragma unroll
            for (int e = 0; e < 4; e++) s[nt][e] = 0.f;
#pragma unroll
        for (int kt = 0; kt < 8; kt++) {
            uint32_t bh[4][4];
#pragma unroll
            for (int kg = 0; kg < 4; kg++) {
                int key = kg * 16 + l8 + ((grp >> 1) << 3);
                int ch  = 2 * kt + (grp & 1);
                uint32_t off = key * 256 + ((((ch ^ key) & 7) | (ch & 8)) << 4);
                ldmx4(bh[kg], sK + off);
            }
#pragma unroll
            for (int nt = 0; nt < 8; nt++)
                mma16816(s[nt], qhf[kt], &bh[nt >> 1][(nt & 1) * 2]);
        }

        // ---- mask + scale: interior fast path (warp-uniform; all 16x64 unmasked) ----
        float bmax0 = -1e30f, bmax1 = -1e30f;
        const bool full = (kb + 63 <= qw) && (kb > qw + 15 - WINDOW);
        if (full) {
#pragma unroll
            for (int nt = 0; nt < 8; nt++) {
                s[nt][0] *= scale; s[nt][1] *= scale;
                s[nt][2] *= scale; s[nt][3] *= scale;
                bmax0 = fmaxf(bmax0, fmaxf(s[nt][0], s[nt][1]));
                bmax1 = fmaxf(bmax1, fmaxf(s[nt][2], s[nt][3]));
            }
        } else {
#pragma unroll
            for (int nt = 0; nt < 8; nt++) {
                int colb = kb + nt * 8 + ln4 * 2;
#pragma unroll
                for (int e = 0; e < 4; e++) {
                    int col = colb + (e & 1);
                    int qp  = (e < 2) ? qpos0 : qpos1;
                    bool ok = (col <= qp) && (col > qp - WINDOW);
                    s[nt][e] = ok ? s[nt][e] * scale : -1e30f;
                }
                bmax0 = fmaxf(bmax0, fmaxf(s[nt][0], s[nt][1]));
                bmax1 = fmaxf(bmax1, fmaxf(s[nt][2], s[nt][3]));
            }
        }
        bmax0 = fmaxf(bmax0, __shfl_xor_sync(0xffffffffu, bmax0, 1));
        bmax0 = fmaxf(bmax0, __shfl_xor_sync(0xffffffffu, bmax0, 2));
        bmax1 = fmaxf(bmax1, __shfl_xor_sync(0xffffffffu, bmax1, 1));
        bmax1 = fmaxf(bmax1, __shfl_xor_sync(0xffffffffu, bmax1, 2));
        float mn0 = fmaxf(m0, bmax0), mn1 = fmaxf(m1, bmax1);
        bool dead0 = mn0 < -1e29f, dead1 = mn1 < -1e29f;
        float corr0 = dead0 ? 1.f : __expf(m0 - mn0);
        float corr1 = dead1 ? 1.f : __expf(m1 - mn1);
        float rs0 = 0.f, rs1 = 0.f;
#pragma unroll
        for (int nt = 0; nt < 8; nt++) {
            s[nt][0] = dead0 ? 0.f : __expf(s[nt][0] - mn0);
            s[nt][1] = dead0 ? 0.f : __expf(s[nt][1] - mn0);
            s[nt][2] = dead1 ? 0.f : __expf(s[nt][2] - mn1);
            s[nt][3] = dead1 ? 0.f : __expf(s[nt][3] - mn1);
            rs0 += s[nt][0] + s[nt][1];
            rs1 += s[nt][2] + s[nt][3];
        }
        rs0 += __shfl_xor_sync(0xffffffffu, rs0, 1);
        rs0 += __shfl_xor_sync(0xffffffffu, rs0, 2);
        rs1 += __shfl_xor_sync(0xffffffffu, rs1, 1);
        rs1 += __shfl_xor_sync(0xffffffffu, rs1, 2);
        l0 = l0 * corr0 + rs0;
        l1 = l1 * corr1 + rs1;
        m0 = mn0; m1 = mn1;
#pragma unroll
        for (int nt = 0; nt < 16; nt++) {
            of[nt][0] *= corr0; of[nt][1] *= corr0;
            of[nt][2] *= corr1; of[nt][3] *= corr1;
        }

#pragma unroll
        for (int kt2 = 0; kt2 < 4; kt2++) {
            uint32_t pah[4], pal[4];
            split2(s[2 * kt2][0],     s[2 * kt2][1],     pah[0], pal[0]);
            split2(s[2 * kt2][2],     s[2 * kt2][3],     pah[1], pal[1]);
            split2(s[2 * kt2 + 1][0], s[2 * kt2 + 1][1], pah[2], pal[2]);
            split2(s[2 * kt2 + 1][2], s[2 * kt2 + 1][3], pah[3], pal[3]);
#pragma unroll
            for (int ntp = 0; ntp < 8; ntp++) {
                uint32_t vhf[4], vlf[4];
                int key = 16 * kt2 + l8 + ((grp & 1) << 3);
                int ch  = 2 * ntp + (grp >> 1);
                uint32_t off = key * 256 + ((((ch ^ key) & 7) | (ch & 8)) << 4);
                ldmx4t(vhf, sVh + off);
                ldmx4t(vlf, sVl + off);
                mma16816(of[2 * ntp],     pah, &vhf[0]);
                mma16816(of[2 * ntp],     pah, &vlf[0]);
                mma16816(of[2 * ntp],     pal, &vhf[0]);
                mma16816(of[2 * ntp + 1], pah, &vhf[2]);
                mma16816(of[2 * ntp + 1], pah, &vlf[2]);
                mma16816(of[2 * ntp + 1], pal, &vhf[2]);
            }
        }
    }

    float il0 = 1.f / l0, il1 = 1.f / l1;
    const int tok0 = b * SEQ + q0 + w * 16 + qd;
#pragma unroll
    for (int nt = 0; nt < 16; nt++) {
        int col = h * HD + nt * 8 + ln4 * 2;
        uint32_t hpk, lpk;
        split2(of[nt][0] * il0, of[nt][1] * il0, hpk, lpk);
        *(uint32_t*)(Oh + (size_t)tok0 * HIDDEN + col) = hpk;
        *(uint32_t*)(Ol + (size_t)tok0 * HIDDEN + col) = lpk;
        split2(of[nt][2] * il1, of[nt][3] * il1, hpk, lpk);
        *(uint32_t*)(Oh + (size_t)(tok0 + 8) * HIDDEN + col) = hpk;
        *(uint32_t*)(Ol + (size_t)(tok0 + 8) * HIDDEN + col) = lpk;
    }
}

// ---------------- launch ----------------------------------------------------------
extern "C" void kernel_launch(void* const* d_in, const int* in_sizes, int n_in,
                              void* d_out, int out_size)
{
    const float* hs = (const float*)d_in[0];
    const float* Wq = (const float*)d_in[2];
    const float* bq = (const float*)d_in[3];
    const float* Wk = (const float*)d_in[4];
    const float* bk = (const float*)d_in[5];
    const float* Wv = (const float*)d_in[6];
    const float* bv = (const float*)d_in[7];
    const float* Wo = (const float*)d_in[8];
    float* out = (float*)d_out;

    void *pxh, *pxl, *pqb, *pkb, *pvh, *pvl, *ptmp;
    void *pwqh, *pwql, *pwkh, *pwkl, *pwvh, *pwvl, *pwoh, *pwol;
    cudaGetSymbolAddress(&pxh, g_xh);
    cudaGetSymbolAddress(&pxl, g_xl);
    cudaGetSymbolAddress(&pqb, g_qb);
    cudaGetSymbolAddress(&pkb, g_kb);
    cudaGetSymbolAddress(&pvh, g_vh);
    cudaGetSymbolAddress(&pvl, g_vl);
    cudaGetSymbolAddress(&ptmp, g_tmp);
    cudaGetSymbolAddress(&pwqh, g_wqh);
    cudaGetSymbolAddress(&pwql, g_wql);
    cudaGetSymbolAddress(&pwkh, g_wkh);
    cudaGetSymbolAddress(&pwkl, g_wkl);
    cudaGetSymbolAddress(&pwvh, g_wvh);
    cudaGetSymbolAddress(&pwvl, g_wvl);
    cudaGetSymbolAddress(&pwoh, g_woh);
    cudaGetSymbolAddress(&pwol, g_wol);
    __nv_bfloat16* xh = (__nv_bfloat16*)pxh;
    __nv_bfloat16* xl = (__nv_bfloat16*)pxl;
    float* vtmp = (float*)ptmp;

    static cudaStream_t s1 = nullptr, s2 = nullptr;
    static cudaEvent_t ev0 = nullptr, evA = nullptr, evRT = nullptr, evK = nullptr,
                       evV = nullptr, evQA = nullptr, evOA = nullptr;
    if (!s1) {
        cudaStreamCreateWithFlags(&s1, cudaStreamNonBlocking);
        cudaStreamCreateWithFlags(&s2, cudaStreamNonBlocking);
        cudaEventCreateWithFlags(&ev0, cudaEventDisableTiming);
        cudaEventCreateWithFlags(&evA, cudaEventDisableTiming);
        cudaEventCreateWithFlags(&evRT, cudaEventDisableTiming);
        cudaEventCreateWithFlags(&evK, cudaEventDisableTiming);
        cudaEventCreateWithFlags(&evV, cudaEventDisableTiming);
        cudaEventCreateWithFlags(&evQA, cudaEventDisableTiming);
        cudaEventCreateWithFlags(&evOA, cudaEventDisableTiming);
    }

    const int SM1 = 3 * 2 * 16384;   // 96KB (NT=2, 3 stages)
    const int SMH = 2 * 3 * 16384;   // 96KB (NT=3, 2 stages)
    cudaFuncSetAttribute((const void*)gemm_mma<2, 1, 2, 3>, cudaFuncAttributeMaxDynamicSharedMemorySize, SM1);
    cudaFuncSetAttribute((const void*)gemm_mma<3, 0, 2, 2>, cudaFuncAttributeMaxDynamicSharedMemorySize, SMH);
    cudaFuncSetAttribute((const void*)gemm_mma<2, 3, 2, 3>, cudaFuncAttributeMaxDynamicSharedMemorySize, SM1);
    cudaFuncSetAttribute((const void*)gemm_mma<2, 4, 2, 3>, cudaFuncAttributeMaxDynamicSharedMemorySize, SM1);
    cudaFuncSetAttribute((const void*)flash_mma, cudaFuncAttributeMaxDynamicSharedMemorySize, FSMEM);

    const int n4h = MTOK * GK / 4;
    dim3 tb(32, 8);

    // fork
    cudaEventRecord(ev0, 0);
    cudaStreamWaitEvent(s1, ev0, 0);
    cudaStreamWaitEvent(s2, ev0, 0);

    // s0: activation split only (minimal serial prefix)
    split_fp32<<<(n4h + 255) / 256, 256>>>((const float4*)hs, xh, xl, n4h);
    cudaEventRecord(evA, 0);

    // s1: rope table (parallel with split), K path
    rope_table<<<(SEQ * 64 + 255) / 256, 256, 0, s1>>>();
    cudaEventRecord(evRT, s1);
    transp_split<<<dim3(KVD / 32, GK / 32), tb, 0, s1>>>(Wk, (__nv_bfloat16*)pwkh, (__nv_bfloat16*)pwkl, KVD);
    cudaStreamWaitEvent(s1, evA, 0);
    gemm_mma<2, 1, 2, 3><<<dim3(KVD / 128, MTOK / 128), 256, SM1, s1>>>(
        xh, nullptr, (__nv_bfloat16*)pwkh, nullptr, bk, nullptr,
        (__nv_bfloat16*)pkb, nullptr, KVD, -1);
    cudaEventRecord(evK, s1);

    // s2: V path split into 2-pass + 1-pass-add (+ Wo transpose)
    transp_split<<<dim3(KVD / 32, GK / 32), tb, 0, s2>>>(Wv, (__nv_bfloat16*)pwvh, (__nv_bfloat16*)pwvl, KVD);
    transp_split<<<dim3(HIDDEN / 32, GK / 32), tb, 0, s2>>>(Wo, (__nv_bfloat16*)pwoh, (__nv_bfloat16*)pwol, HIDDEN);
    cudaStreamWaitEvent(s2, evA, 0);
    gemm_mma<3, 0, 2, 2><<<dim3(KVD / 128, MTOK / 128), 256, SMH, s2>>>(
        xh, xl, (__nv_bfloat16*)pwvh, nullptr, bv, vtmp,
        nullptr, nullptr, KVD, -1);
    gemm_mma<2, 4, 2, 3><<<dim3(KVD / 128, MTOK / 128), 256, SM1, s2>>>(
        xh, nullptr, (__nv_bfloat16*)pwvl, nullptr, nullptr, vtmp,
        (__nv_bfloat16*)pvh, (__nv_bfloat16*)pvl, KVD, -1);
    cudaEventRecord(evV, s2);

    // s0: Q path, token-half A then B
    transp_split<<<dim3(HIDDEN / 32, GK / 32), tb>>>(Wq, (__nv_bfloat16*)pwqh, (__nv_bfloat16*)pwql, HIDDEN);
    cudaStreamWaitEvent(0, evRT, 0);
    gemm_mma<2, 1, 2, 3><<<dim3(HIDDEN / 128, 16), 256, SM1>>>(
        xh, nullptr, (__nv_bfloat16*)pwqh, nullptr, bq, nullptr,
        (__nv_bfloat16*)pqb, nullptr, HIDDEN, 0);
    cudaEventRecord(evQA, 0);
    gemm_mma<2, 1, 2, 3><<<dim3(HIDDEN / 128, 16), 256, SM1>>>(
        xh, nullptr, (__nv_bfloat16*)pwqh, nullptr, bq, nullptr,
        (__nv_bfloat16*)pqb, nullptr, HIDDEN, 1);

    // s1: flashA || Q-projB, then O-projA (two 2-CTA/SM kernels)
    cudaStreamWaitEvent(s1, evQA, 0);
    cudaStreamWaitEvent(s1, evV, 0);
    flash_mma<<<dim3(16, NH, BATCH), 128, FSMEM, s1>>>(
        (__nv_bfloat16*)pqb, (__nv_bfloat16*)pkb,
        (__nv_bfloat16*)pvh, (__nv_bfloat16*)pvl, xh, xl, 0);
    gemm_mma<3, 0, 2, 2><<<dim3(HIDDEN / 128, 16), 256, SMH, s1>>>(
        xh, xl, (__nv_bfloat16*)pwoh, nullptr, nullptr, out,
        nullptr, nullptr, HIDDEN, 0);
    gemm_mma<2, 3, 2, 3><<<dim3(HIDDEN / 128, 16), 256, SM1, s1>>>(
        xh, nullptr, (__nv_bfloat16*)pwol, nullptr, nullptr, out,
        nullptr, nullptr, HIDDEN, 0);
    cudaEventRecord(evOA, s1);

    // s0: flashB, then O-projB
    cudaStreamWaitEvent(0, evK, 0);
    cudaStreamWaitEvent(0, evV, 0);
    flash_mma<<<dim3(16, NH, BATCH), 128, FSMEM>>>(
        (__nv_bfloat16*)pqb, (__nv_bfloat16*)pkb,
        (__nv_bfloat16*)pvh, (__nv_bfloat16*)pvl, xh, xl, 16);
    gemm_mma<3, 0, 2, 2><<<dim3(HIDDEN / 128, 16), 256, SMH>>>(
        xh, xl, (__nv_bfloat16*)pwoh, nullptr, nullptr, out,
        nullptr, nullptr, HIDDEN, 1);
    gemm_mma<2, 3, 2, 3><<<dim3(HIDDEN / 128, 16), 256, SM1>>>(
        xh, nullptr, (__nv_bfloat16*)pwol, nullptr, nullptr, out,
        nullptr, nullptr, HIDDEN, 1);

    // join s1 back to the origin stream
    cudaStreamWaitEvent(0, evOA, 0);
}